// round 12
// baseline (speedup 1.0000x reference)
#include <cuda_runtime.h>
#include <cuda_fp16.h>
#include <math.h>
#include <stdint.h>

#define SEQ 1024
#define DM  768
#define NHEAD 12
#define HDIM 64
#define NLAYERS 4
#define DFF 3072

// ---------------- scratch (static device memory; no runtime allocs) ----------------
__device__ __half g_relsum[(size_t)SEQ * SEQ * HDIM];         // 128 MB (fp16)
__device__ float  g_scores[(size_t)NHEAD * SEQ * SEQ];        // 48 MB (fp32 logits)
__device__ __half g_probs[(size_t)NHEAD * SEQ * SEQ];         // 24 MB (fp16 probs)
__device__ float  g_part[4 * SEQ * DM];                       // split-K partials
__device__ __half g_h16[SEQ * DM];
__device__ __half g_hbuf[SEQ * DM];
__device__ __half g_q[NHEAD * SEQ * HDIM];
__device__ __half g_k[NHEAD * SEQ * HDIM];
__device__ __half g_vt[NHEAD * HDIM * SEQ];
__device__ __half g_ctx[SEQ * DM];
__device__ __half g_attn[SEQ * DM];
__device__ __half g_inter[SEQ * DFF];
// fp16 weights (converted once per launch)
__device__ __half g_wq16[NLAYERS * DM * DM];
__device__ __half g_wk16[NLAYERS * DM * DM];
__device__ __half g_wv16[NLAYERS * DM * DM];
__device__ __half g_wo16[NLAYERS * DM * DM];
__device__ __half g_wi16[NLAYERS * DFF * DM];
__device__ __half g_w216[NLAYERS * DM * DFF];

// ---------------- helpers ----------------
__device__ __forceinline__ float warpRedMax(float v) {
#pragma unroll
    for (int o = 16; o > 0; o >>= 1) v = fmaxf(v, __shfl_xor_sync(0xffffffffu, v, o));
    return v;
}
__device__ __forceinline__ float warpRedSum(float v) {
#pragma unroll
    for (int o = 16; o > 0; o >>= 1) v += __shfl_xor_sync(0xffffffffu, v, o);
    return v;
}
__device__ __forceinline__ void cp16(uint32_t dst, const void* src) {
    asm volatile("cp.async.cg.shared.global [%0], [%1], 16;" :: "r"(dst), "l"(src));
}
__device__ __forceinline__ void mma_f16(float* c, const uint32_t* a, const uint32_t* b) {
    asm volatile(
        "mma.sync.aligned.m16n8k16.row.col.f32.f16.f16.f32 "
        "{%0,%1,%2,%3}, {%4,%5,%6,%7}, {%8,%9}, {%0,%1,%2,%3};"
        : "+f"(c[0]), "+f"(c[1]), "+f"(c[2]), "+f"(c[3])
        : "r"(a[0]), "r"(a[1]), "r"(a[2]), "r"(a[3]), "r"(b[0]), "r"(b[1]));
}
__device__ __forceinline__ void ldsm_x4(uint32_t& r0, uint32_t& r1, uint32_t& r2, uint32_t& r3,
                                        uint32_t addr) {
    asm volatile("ldmatrix.sync.aligned.m8n8.x4.shared.b16 {%0,%1,%2,%3}, [%4];"
                 : "=r"(r0), "=r"(r1), "=r"(r2), "=r"(r3) : "r"(addr));
}
__device__ __forceinline__ uint2 f4_to_h4(float4 x) {
    __half2 h0 = __floats2half2_rn(x.x, x.y);
    __half2 h1 = __floats2half2_rn(x.z, x.w);
    uint2 o; o.x = *(uint32_t*)&h0; o.y = *(uint32_t*)&h1;
    return o;
}

// ---------------- one-shot fp32 -> fp16 conversions ----------------
__global__ void __launch_bounds__(256) f2h1_kernel(
    const float4* __restrict__ s, uint2* __restrict__ d)
{
    const int i = blockIdx.x * 256 + threadIdx.x;
    d[i] = f4_to_h4(s[i]);
}
__global__ void __launch_bounds__(256) f2h4_kernel(
    const float4* __restrict__ s0, const float4* __restrict__ s1,
    const float4* __restrict__ s2, const float4* __restrict__ s3,
    uint2* __restrict__ d0, uint2* __restrict__ d1,
    uint2* __restrict__ d2, uint2* __restrict__ d3)
{
    const int i = blockIdx.x * 256 + threadIdx.x;
    const int z = blockIdx.z;
    const float4* s = (z == 0) ? s0 : (z == 1) ? s1 : (z == 2) ? s2 : s3;
    uint2* d        = (z == 0) ? d0 : (z == 1) ? d1 : (z == 2) ? d2 : d3;
    d[i] = f4_to_h4(s[i]);
}
__global__ void __launch_bounds__(256) f2h2_kernel(
    const float4* __restrict__ s0, const float4* __restrict__ s1,
    uint2* __restrict__ d0, uint2* __restrict__ d1)
{
    const int i = blockIdx.x * 256 + threadIdx.x;
    const float4* s = blockIdx.z ? s1 : s0;
    uint2* d        = blockIdx.z ? d1 : d0;
    d[i] = f4_to_h4(s[i]);
}

// ================= 128x128 fp16 GEMM mainloop (256 threads, warp tile 64x32, 3-stage) =================
#define T_ST 9216    // halves per stage per matrix (128 rows x 72 pitch)
#define GEMM_SMEM (3 * T_ST * 2 * 2)   // 110592 B

__device__ __forceinline__ void hgemm_mainloop128(
    const __half* __restrict__ Ag, const __half* __restrict__ Wg,
    __half* __restrict__ sm, int Kloop, int lda, int ldw, float acc[4][4][4])
{
    const int tid = threadIdx.x;
    const int srow = tid >> 3;          // 0..31
    const int scol = (tid & 7) << 3;

    __half* As = sm;
    __half* Ws = sm + 3 * T_ST;

    const uint32_t asB = (uint32_t)__cvta_generic_to_shared(As);
    const uint32_t wsB = (uint32_t)__cvta_generic_to_shared(Ws);
    const uint32_t sa0 = asB + (uint32_t)(srow * 72 + scol) * 2u;
    const uint32_t sw0 = wsB + (uint32_t)(srow * 72 + scol) * 2u;

    const __half* Agp = Ag + (long long)srow * lda + scol;
    const __half* Wgp = Wg + (long long)srow * ldw + scol;

    const int KT = Kloop >> 6;

#pragma unroll
    for (int st = 0; st < 2; st++) {
        if (st < KT) {
#pragma unroll
            for (int p = 0; p < 4; p++) {
                cp16(sa0 + (uint32_t)(st * T_ST + p * 32 * 72) * 2u, Agp + (long long)(p * 32) * lda + st * 64);
                cp16(sw0 + (uint32_t)(st * T_ST + p * 32 * 72) * 2u, Wgp + (long long)(p * 32) * ldw + st * 64);
            }
        }
        asm volatile("cp.async.commit_group;");
    }

    const int wid = tid >> 5, lane = tid & 31;
    const int wm = wid & 1, wn = wid >> 1;          // 2 x 4 warps; warp tile 64x32
    const int a_row = wm * 64 + (lane & 15);
    const int a_ko  = (lane >> 4) << 3;
    const int b_row = wn * 32 + (lane & 7) + ((lane >> 4) << 3);
    const int b_ko  = ((lane >> 3) & 1) << 3;

    const uint32_t aF = asB + (uint32_t)(a_row * 72 + a_ko) * 2u;
    const uint32_t wF = wsB + (uint32_t)(b_row * 72 + b_ko) * 2u;

    for (int kt = 0; kt < KT; kt++) {
        asm volatile("cp.async.wait_group 1;");
        __syncthreads();

        const int pf = kt + 2;
        if (pf < KT) {
            const int st = pf % 3;
#pragma unroll
            for (int p = 0; p < 4; p++) {
                cp16(sa0 + (uint32_t)(st * T_ST + p * 32 * 72) * 2u, Agp + (long long)(p * 32) * lda + pf * 64);
                cp16(sw0 + (uint32_t)(st * T_ST + p * 32 * 72) * 2u, Wgp + (long long)(p * 32) * ldw + pf * 64);
            }
        }
        asm volatile("cp.async.commit_group;");

        const uint32_t aS = aF + (uint32_t)((kt % 3) * T_ST) * 2u;
        const uint32_t wS = wF + (uint32_t)((kt % 3) * T_ST) * 2u;

#pragma unroll
        for (int ks = 0; ks < 4; ks++) {
            uint32_t a[4][4], b[2][4];
#pragma unroll
            for (int mt = 0; mt < 4; mt++)
                ldsm_x4(a[mt][0], a[mt][1], a[mt][2], a[mt][3],
                        aS + (uint32_t)(mt * 16 * 72 + ks * 16) * 2u);
#pragma unroll
            for (int nt2 = 0; nt2 < 2; nt2++)
                ldsm_x4(b[nt2][0], b[nt2][1], b[nt2][2], b[nt2][3],
                        wS + (uint32_t)(nt2 * 16 * 72 + ks * 16) * 2u);
#pragma unroll
            for (int mt = 0; mt < 4; mt++)
#pragma unroll
                for (int nt = 0; nt < 4; nt++) {
                    uint32_t bb[2] = { b[nt >> 1][(nt & 1) * 2], b[nt >> 1][(nt & 1) * 2 + 1] };
                    mma_f16(acc[mt][nt], a[mt], bb);
                }
        }
    }
}

// ================= 128x64 fp16 GEMM mainloop (for PV, N=64) =================
#define A_ST 9216
#define W_ST 4608
#define GEMM_SMEM64 ((3 * A_ST + 3 * W_ST) * 2)   // 82944 B

__device__ __forceinline__ void hgemm_mainloop64(
    const __half* __restrict__ Ag, const __half* __restrict__ Wg,
    __half* __restrict__ sm, int Kloop, int lda, int ldw, float acc[2][4][4])
{
    const int tid = threadIdx.x;
    const int srow = tid >> 3;
    const int scol = (tid & 7) << 3;

    __half* As = sm;
    __half* Ws = sm + 3 * A_ST;

    const uint32_t asB = (uint32_t)__cvta_generic_to_shared(As);
    const uint32_t wsB = (uint32_t)__cvta_generic_to_shared(Ws);
    const uint32_t sa0 = asB + (uint32_t)(srow * 72 + scol) * 2u;
    const uint32_t sw0 = wsB + (uint32_t)(srow * 72 + scol) * 2u;

    const __half* Agp = Ag + (long long)srow * lda + scol;
    const __half* Wgp = Wg + (long long)srow * ldw + scol;

    const int KT = Kloop >> 6;

#pragma unroll
    for (int st = 0; st < 2; st++) {
        if (st < KT) {
#pragma unroll
            for (int p = 0; p < 4; p++)
                cp16(sa0 + (uint32_t)(st * A_ST + p * 32 * 72) * 2u, Agp + (long long)(p * 32) * lda + st * 64);
#pragma unroll
            for (int p = 0; p < 2; p++)
                cp16(sw0 + (uint32_t)(st * W_ST + p * 32 * 72) * 2u, Wgp + (long long)(p * 32) * ldw + st * 64);
        }
        asm volatile("cp.async.commit_group;");
    }

    const int wid = tid >> 5, lane = tid & 31;
    const int wm = wid & 3, wn = wid >> 2;
    const int a_row = wm * 32 + (lane & 15);
    const int a_ko  = (lane >> 4) << 3;
    const int b_row = wn * 32 + (lane & 7) + ((lane >> 4) << 3);
    const int b_ko  = ((lane >> 3) & 1) << 3;

    const uint32_t aF = asB + (uint32_t)(a_row * 72 + a_ko) * 2u;
    const uint32_t wF = wsB + (uint32_t)(b_row * 72 + b_ko) * 2u;

    for (int kt = 0; kt < KT; kt++) {
        asm volatile("cp.async.wait_group 1;");
        __syncthreads();

        const int pf = kt + 2;
        if (pf < KT) {
            const int st = pf % 3;
#pragma unroll
            for (int p = 0; p < 4; p++)
                cp16(sa0 + (uint32_t)(st * A_ST + p * 32 * 72) * 2u, Agp + (long long)(p * 32) * lda + pf * 64);
#pragma unroll
            for (int p = 0; p < 2; p++)
                cp16(sw0 + (uint32_t)(st * W_ST + p * 32 * 72) * 2u, Wgp + (long long)(p * 32) * ldw + pf * 64);
        }
        asm volatile("cp.async.commit_group;");

        const uint32_t aS = aF + (uint32_t)((kt % 3) * A_ST) * 2u;
        const uint32_t wS = wF + (uint32_t)((kt % 3) * W_ST) * 2u;

#pragma unroll
        for (int ks = 0; ks < 4; ks++) {
            uint32_t a[2][4], b[2][4];
#pragma unroll
            for (int mt = 0; mt < 2; mt++)
                ldsm_x4(a[mt][0], a[mt][1], a[mt][2], a[mt][3],
                        aS + (uint32_t)(mt * 16 * 72 + ks * 16) * 2u);
#pragma unroll
            for (int nt2 = 0; nt2 < 2; nt2++)
                ldsm_x4(b[nt2][0], b[nt2][1], b[nt2][2], b[nt2][3],
                        wS + (uint32_t)(nt2 * 16 * 72 + ks * 16) * 2u);
#pragma unroll
            for (int mt = 0; mt < 2; mt++)
#pragma unroll
                for (int nt = 0; nt < 4; nt++) {
                    uint32_t bb[2] = { b[nt >> 1][(nt & 1) * 2], b[nt >> 1][(nt & 1) * 2 + 1] };
                    mma_f16(acc[mt][nt], a[mt], bb);
                }
        }
    }
}

// ---------------- generic fp16 GEMM (128x128 tiles, z-batched) ----------------
template<int EPI, int F32OUT>
__global__ void __launch_bounds__(256) hgemm_g(
    const __half* __restrict__ A, const __half* __restrict__ W,
    const float* __restrict__ bias, void* __restrict__ Cv,
    int K, int ldC, long long sA, long long sW, long long sC)
{
    extern __shared__ __half smh[];
    const int bz = blockIdx.z;
    const int m0 = blockIdx.y << 7, n0 = blockIdx.x << 7;

    float acc[4][4][4];
#pragma unroll
    for (int i = 0; i < 4; i++)
#pragma unroll
        for (int j = 0; j < 4; j++)
#pragma unroll
            for (int l = 0; l < 4; l++) acc[i][j][l] = 0.f;

    hgemm_mainloop128(A + sA * bz + (long long)m0 * K,
                      W + sW * bz + (long long)n0 * K, smh, K, K, K, acc);

    const int tid = threadIdx.x, wid = tid >> 5, lane = tid & 31;
    const int wm = wid & 1, wn = wid >> 1, g = lane >> 2, t = lane & 3;

#pragma unroll
    for (int mt = 0; mt < 4; mt++) {
        const int rb = m0 + wm * 64 + mt * 16 + g;
#pragma unroll
        for (int nt = 0; nt < 4; nt++) {
            const int cb = n0 + wn * 32 + nt * 8 + 2 * t;
#pragma unroll
            for (int hf = 0; hf < 2; hf++) {
                const int m = rb + hf * 8;
                float v0 = acc[mt][nt][hf * 2 + 0];
                float v1 = acc[mt][nt][hf * 2 + 1];
                if (bias) { v0 += bias[cb]; v1 += bias[cb + 1]; }
                if (EPI == 1) {
                    v0 = 0.5f * v0 * (1.0f + erff(v0 * 0.70710678118654752f));
                    v1 = 0.5f * v1 * (1.0f + erff(v1 * 0.70710678118654752f));
                }
                if (F32OUT) {
                    float* C = (float*)Cv + sC * bz;
                    *(float2*)&C[(long long)m * ldC + cb] = make_float2(v0, v1);
                } else {
                    __half* C = (__half*)Cv + sC * bz;
                    __half2 h2 = __floats2half2_rn(v0, v1);
                    *(__half2*)&C[(long long)m * ldC + cb] = h2;
                }
            }
        }
    }
}

// ---------------- split-K GEMM (128x128): part[ks] = A[:, ks*Ksplit:+Ksplit] @ W^T ----------------
__global__ void __launch_bounds__(256) hgemm_sk(
    const __half* __restrict__ A, const __half* __restrict__ W,
    float* __restrict__ part, int Kfull, int Ksplit)
{
    extern __shared__ __half smh[];
    const int ks = blockIdx.z;
    const int m0 = blockIdx.y << 7, n0 = blockIdx.x << 7;

    float acc[4][4][4];
#pragma unroll
    for (int i = 0; i < 4; i++)
#pragma unroll
        for (int j = 0; j < 4; j++)
#pragma unroll
            for (int l = 0; l < 4; l++) acc[i][j][l] = 0.f;

    hgemm_mainloop128(A + (long long)m0 * Kfull + (long long)ks * Ksplit,
                      W + (long long)n0 * Kfull + (long long)ks * Ksplit,
                      smh, Ksplit, Kfull, Kfull, acc);

    float* C = part + (long long)ks * (SEQ * DM);

    const int tid = threadIdx.x, wid = tid >> 5, lane = tid & 31;
    const int wm = wid & 1, wn = wid >> 1, g = lane >> 2, t = lane & 3;

#pragma unroll
    for (int mt = 0; mt < 4; mt++) {
        const int rb = m0 + wm * 64 + mt * 16 + g;
#pragma unroll
        for (int nt = 0; nt < 4; nt++) {
            const int cb = n0 + wn * 32 + nt * 8 + 2 * t;
#pragma unroll
            for (int hf = 0; hf < 2; hf++) {
                const int m = rb + hf * 8;
                *(float2*)&C[(long long)m * DM + cb] =
                    make_float2(acc[mt][nt][hf * 2 + 0], acc[mt][nt][hf * 2 + 1]);
            }
        }
    }
}

// ---------------- fused QKV projection (128x128) ----------------
__global__ void __launch_bounds__(256) hqkv_kernel(
    const __half* __restrict__ h,
    const __half* __restrict__ Wq, const __half* __restrict__ Wk, const __half* __restrict__ Wv,
    const float* __restrict__ bq, const float* __restrict__ bk, const float* __restrict__ bv,
    __half* __restrict__ qo, __half* __restrict__ ko, __half* __restrict__ vto)
{
    extern __shared__ __half smh[];
    const int z = blockIdx.z;
    const __half* W   = (z == 0) ? Wq : (z == 1) ? Wk : Wv;
    const float* bias = (z == 0) ? bq : (z == 1) ? bk : bv;
    __half* out       = (z == 0) ? qo : (z == 1) ? ko : vto;
    const float scale = (z == 0) ? 0.125f : 1.0f;
    const int m0 = blockIdx.y << 7, n0 = blockIdx.x << 7;

    float acc[4][4][4];
#pragma unroll
    for (int i = 0; i < 4; i++)
#pragma unroll
        for (int j = 0; j < 4; j++)
#pragma unroll
            for (int l = 0; l < 4; l++) acc[i][j][l] = 0.f;

    hgemm_mainloop128(h + (long long)m0 * DM, W + (long long)n0 * DM, smh, DM, DM, DM, acc);

    const int tid = threadIdx.x, wid = tid >> 5, lane = tid & 31;
    const int wm = wid & 1, wn = wid >> 1, g = lane >> 2, t = lane & 3;

#pragma unroll
    for (int mt = 0; mt < 4; mt++) {
        const int rb = m0 + wm * 64 + mt * 16 + g;
#pragma unroll
        for (int nt = 0; nt < 4; nt++) {
            const int cb = n0 + wn * 32 + nt * 8 + 2 * t;
#pragma unroll
            for (int hf = 0; hf < 2; hf++) {
                const int m = rb + hf * 8;
                float v0 = (acc[mt][nt][hf * 2 + 0] + bias[cb]) * scale;
                float v1 = (acc[mt][nt][hf * 2 + 1] + bias[cb + 1]) * scale;
                if (z < 2) {
                    const long long idx = ((long long)(cb >> 6) << 16) + (long long)m * 64 + (cb & 63);
                    __half2 h2 = __floats2half2_rn(v0, v1);
                    *(__half2*)&out[idx] = h2;
                } else {
                    out[(long long)cb * 1024 + m]       = __float2half(v0);
                    out[(long long)(cb + 1) * 1024 + m] = __float2half(v1);
                }
            }
        }
    }
}

// ---------------- PV split-K GEMM (128x64 path, N=64) ----------------
__global__ void __launch_bounds__(256, 2) hgemm_pv(
    const __half* __restrict__ probs, const __half* __restrict__ vt, float* __restrict__ part)
{
    extern __shared__ __half smh[];
    const int ks = blockIdx.x;
    const int m0 = blockIdx.y << 7;
    const int hd = blockIdx.z;

    float acc[2][4][4];
#pragma unroll
    for (int i = 0; i < 2; i++)
#pragma unroll
        for (int j = 0; j < 4; j++)
#pragma unroll
            for (int l = 0; l < 4; l++) acc[i][j][l] = 0.f;

    hgemm_mainloop64(probs + (long long)hd * 1048576 + (long long)m0 * 1024 + ks * 256,
                     vt + (long long)hd * 65536 + ks * 256,
                     smh, 256, 1024, 1024, acc);

    float* C = part + (long long)ks * 786432 + hd * 64;

    const int tid = threadIdx.x, wid = tid >> 5, lane = tid & 31;
    const int wm = wid & 3, wn = wid >> 2, g = lane >> 2, t = lane & 3;

#pragma unroll
    for (int mt = 0; mt < 2; mt++) {
        const int rb = m0 + wm * 32 + mt * 16 + g;
#pragma unroll
        for (int nt = 0; nt < 4; nt++) {
            const int cb = wn * 32 + nt * 8 + 2 * t;
#pragma unroll
            for (int hf = 0; hf < 2; hf++) {
                const int m = rb + hf * 8;
                *(float2*)&C[(long long)m * 768 + cb] =
                    make_float2(acc[mt][nt][hf * 2 + 0], acc[mt][nt][hf * 2 + 1]);
            }
        }
    }
}

// ---------------- PV reduce: ctx(fp16) = sum of 4 fp32 partials ----------------
__global__ void __launch_bounds__(256) pv_reduce(
    const float4* __restrict__ part, uint2* __restrict__ ctx)
{
    const int i = blockIdx.x * 256 + threadIdx.x;
    float4 a = part[i];
    const float4 b = part[i + 196608];
    const float4 c = part[i + 393216];
    const float4 d = part[i + 589824];
    a.x += b.x + c.x + d.x; a.y += b.y + c.y + d.y;
    a.z += b.z + c.z + d.z; a.w += b.w + c.w + d.w;
    ctx[i] = f4_to_h4(a);
}

// ---------------- shared softmax epilogue (warp-parallel) ----------------
#define SC_PITCH 1032
#define RS_QPITCH 72
#define RS_RPITCH 72

__device__ __forceinline__ void softmax_epilogue(
    const float* __restrict__ sscores, const float* __restrict__ smask,
    __half* __restrict__ probs, int s, int wid, int lane)
{
#pragma unroll
    for (int hh = 0; hh < 2; hh++) {
        if (hh == 1 && wid >= 4) break;
        const int n = hh ? (8 + wid) : wid;

        float4 v[8];
        float m = -1e30f;
#pragma unroll
        for (int j = 0; j < 8; j++) {
            const int c4 = (lane + 32 * j) << 2;
            float4 a = *(const float4*)&sscores[n * SC_PITCH + c4];
            const float4 mk = *(const float4*)&smask[c4];
            a.x += mk.x; a.y += mk.y; a.z += mk.z; a.w += mk.w;
            v[j] = a;
            m = fmaxf(m, fmaxf(fmaxf(a.x, a.y), fmaxf(a.z, a.w)));
        }
        m = warpRedMax(m);

        float sum = 0.f;
#pragma unroll
        for (int j = 0; j < 8; j++) {
            v[j].x = __expf(v[j].x - m); v[j].y = __expf(v[j].y - m);
            v[j].z = __expf(v[j].z - m); v[j].w = __expf(v[j].w - m);
            sum += v[j].x + v[j].y + v[j].z + v[j].w;
        }
        sum = warpRedSum(sum);
        const float inv = 1.0f / sum;

        __half* prow = probs + (((long long)n << 10) + s) * 1024;
#pragma unroll
        for (int j = 0; j < 8; j++) {
            const int c4 = (lane + 32 * j) << 2;
            __half2 p0 = __floats2half2_rn(v[j].x * inv, v[j].y * inv);
            __half2 p1 = __floats2half2_rn(v[j].z * inv, v[j].w * inv);
            uint2 o; o.x = *(uint32_t*)&p0; o.y = *(uint32_t*)&p1;
            *(uint2*)&prow[c4] = o;
        }
    }
}

// ---------------- layer-0 fused: relsum build + rel-score + mask + softmax ----------------
#define RS0_SMEM 74368

__global__ void __launch_bounds__(256) rs0_kernel(
    const float4* __restrict__ r0, const float4* __restrict__ r1,
    const float4* __restrict__ r2, uint2* __restrict__ rsum,
    const __half* __restrict__ qb, const float* __restrict__ scores,
    __half* __restrict__ probs, const float* __restrict__ mask)
{
    extern __shared__ char smc[];
    __half* qs      = (__half*)smc;
    float*  sscores = (float*)(smc + 2304);
    float*  smask   = (float*)(smc + 51840);
    __half* relb    = (__half*)(smc + 55936);

    const int s = blockIdx.x;
    const int tid = threadIdx.x;
    const int wid = tid >> 5, lane = tid & 31;
    const int g = lane >> 2, t = lane & 3;

    {
        const uint32_t ss_s = (uint32_t)__cvta_generic_to_shared(sscores);
#pragma unroll
        for (int p = 0; p < 12; p++) {
            const int idx = tid + 256 * p;
            const int n = idx >> 8, c4 = (idx & 255) << 2;
            cp16(ss_s + (uint32_t)(n * SC_PITCH + c4) * 4u,
                 scores + (((long long)n << 10) + s) * 1024 + c4);
        }
        cp16((uint32_t)__cvta_generic_to_shared(smask) + (uint32_t)(tid << 4),
             mask + (tid << 2));
        asm volatile("cp.async.commit_group;");
    }

    for (int i = tid; i < 16 * 64; i += 256) {
        const int r = i >> 6, c = i & 63;
        qs[r * RS_QPITCH + c] = (r < 12) ? qb[((long long)r << 16) + (s << 6) + c] : __float2half(0.f);
    }

    const long long base = ((long long)s << 14);
    float4 ra[4], rb4[4], rc[4];
#pragma unroll
    for (int p = 0; p < 4; p++) {
        const long long idx = base + tid + 256 * p;
        ra[p] = r0[idx]; rb4[p] = r1[idx]; rc[p] = r2[idx];
    }

    asm volatile("cp.async.wait_group 0;");
    __syncthreads();

    uint32_t afrag[4][4];
#pragma unroll
    for (int ks = 0; ks < 4; ks++) {
        afrag[ks][0] = *(const uint32_t*)&qs[g * RS_QPITCH + ks * 16 + 2 * t];
        afrag[ks][1] = *(const uint32_t*)&qs[(g + 8) * RS_QPITCH + ks * 16 + 2 * t];
        afrag[ks][2] = *(const uint32_t*)&qs[g * RS_QPITCH + ks * 16 + 2 * t + 8];
        afrag[ks][3] = *(const uint32_t*)&qs[(g + 8) * RS_QPITCH + ks * 16 + 2 * t + 8];
    }

    const int lrb = wid * 8;
    const int lr  = lrb + g;

    for (int ch = 0; ch < 16; ch++) {
        __half* rbuf = relb + (ch & 1) * (64 * RS_RPITCH);
#pragma unroll
        for (int p = 0; p < 4; p++) {
            float4 x = ra[p];
            x.x += rb4[p].x + rc[p].x; x.y += rb4[p].y + rc[p].y;
            x.z += rb4[p].z + rc[p].z; x.w += rb4[p].w + rc[p].w;
            const uint2 hv = f4_to_h4(x);
            const int il = tid + 256 * p;
            const int r = il >> 4, c4 = (il & 15) << 2;
            *(uint2*)&rbuf[r * RS_RPITCH + c4] = hv;
            rsum[base + (long long)ch * 1024 + il] = hv;
        }
        __syncthreads();

        if (ch + 1 < 16) {
#pragma unroll
            for (int p = 0; p < 4; p++) {
                const long long idx = base + (long long)(ch + 1) * 1024 + tid + 256 * p;
                ra[p] = r0[idx]; rb4[p] = r1[idx]; rc[p] = r2[idx];
            }
        }

        float c[4] = {0.f, 0.f, 0.f, 0.f};
#pragma unroll
        for (int ks = 0; ks < 4; ks++) {
            uint32_t bb[2];
            bb[0] = *(const uint32_t*)&rbuf[lr * RS_RPITCH + ks * 16 + 2 * t];
            bb[1] = *(const uint32_t*)&rbuf[lr * RS_RPITCH + ks * 16 + 2 * t + 8];
            mma_f16(c, afrag[ks], bb);
        }
        const int kc = ch * 64 + lrb + 2 * t;
        float2 o0 = *(float2*)&sscores[g * SC_PITCH + kc];
        o0.x += c[0]; o0.y += c[1];
        *(float2*)&sscores[g * SC_PITCH + kc] = o0;
        if (g < 4) {
            float2 o1 = *(float2*)&sscores[(g + 8) * SC_PITCH + kc];
            o1.x += c[2]; o1.y += c[3];
            *(float2*)&sscores[(g + 8) * SC_PITCH + kc] = o1;
        }
    }
    __syncthreads();

    softmax_epilogue(sscores, smask, probs, s, wid, lane);
}

// ---------------- layers 1-3: rel-score + mask + softmax ----------------
#define RS_CROWS 64
#define RS_CHUNK_H (RS_CROWS * RS_RPITCH)
#define RS_NBUF 6
#define RS_NCHUNK 16
#define RS_SMEM 111232

__global__ void __launch_bounds__(256) rel_softmax_kernel(
    const __half* __restrict__ rel, const __half* __restrict__ qb,
    const float* __restrict__ scores, __half* __restrict__ probs,
    const float* __restrict__ mask)
{
    extern __shared__ char smc[];
    __half* qs      = (__half*)smc;
    float*  sscores = (float*)(smc + 2304);
    float*  smask   = (float*)(smc + 51840);
    __half* relb    = (__half*)(smc + 55936);

    const int s = blockIdx.x;
    const int tid = threadIdx.x;
    const int wid = tid >> 5, lane = tid & 31;
    const int g = lane >> 2, t = lane & 3;

    {
        const uint32_t ss_s = (uint32_t)__cvta_generic_to_shared(sscores);
#pragma unroll
        for (int p = 0; p < 12; p++) {
            const int idx = tid + 256 * p;
            const int n = idx >> 8, c4 = (idx & 255) << 2;
            cp16(ss_s + (uint32_t)(n * SC_PITCH + c4) * 4u,
                 scores + (((long long)n << 10) + s) * 1024 + c4);
        }
        cp16((uint32_t)__cvta_generic_to_shared(smask) + (uint32_t)(tid << 4),
             mask + (tid << 2));
        asm volatile("cp.async.commit_group;");
    }

    for (int i = tid; i < 16 * 64; i += 256) {
        const int r = i >> 6, c = i & 63;
        qs[r * RS_QPITCH + c] = (r < 12) ? qb[((long long)r << 16) + (s << 6) + c] : __float2half(0.f);
    }

    const __half* relS = rel + ((long long)s << 16);
    const uint32_t relb_s = (uint32_t)__cvta_generic_to_shared(relb);

#pragma unroll
    for (int ch = 0; ch < RS_NBUF - 1; ch++) {
        const uint32_t dstb = relb_s + (uint32_t)(ch * RS_CHUNK_H) * 2u;
        const __half* src = relS + (long long)ch * RS_CROWS * 64;
#pragma unroll
        for (int p = 0; p < 2; p++) {
            const int idx = tid + 256 * p;
            const int r = idx >> 3, c8 = (idx & 7) << 3;
            cp16(dstb + (uint32_t)(r * RS_RPITCH + c8) * 2u, src + (long long)r * 64 + c8);
        }
        asm volatile("cp.async.commit_group;");
    }

    __syncthreads();

    uint32_t afrag[4][4];
#pragma unroll
    for (int ks = 0; ks < 4; ks++) {
        afrag[ks][0] = *(const uint32_t*)&qs[g * RS_QPITCH + ks * 16 + 2 * t];
        afrag[ks][1] = *(const uint32_t*)&qs[(g + 8) * RS_QPITCH + ks * 16 + 2 * t];
        afrag[ks][2] = *(const uint32_t*)&qs[g * RS_QPITCH + ks * 16 + 2 * t + 8];
        afrag[ks][3] = *(const uint32_t*)&qs[(g + 8) * RS_QPITCH + ks * 16 + 2 * t + 8];
    }

    const int lrb = wid * 8;
    const int lr  = lrb + g;

    for (int ch = 0; ch < RS_NCHUNK; ch++) {
        asm volatile("cp.async.wait_group 4;");
        __syncthreads();

        const int pf = ch + RS_NBUF - 1;
        if (pf < RS_NCHUNK) {
            const uint32_t dstb = relb_s + (uint32_t)((pf % RS_NBUF) * RS_CHUNK_H) * 2u;
            const __half* src = relS + (long long)pf * RS_CROWS * 64;
#pragma unroll
            for (int p = 0; p < 2; p++) {
                const int idx = tid + 256 * p;
                const int r = idx >> 3, c8 = (idx & 7) << 3;
                cp16(dstb + (uint32_t)(r * RS_RPITCH + c8) * 2u, src + (long long)r * 64 + c8);
            }
        }
        asm volatile("cp.async.commit_group;");

        const __half* rb = relb + (ch % RS_NBUF) * RS_CHUNK_H;
        float c[4] = {0.f, 0.f, 0.f, 0.f};
#pragma unroll
        for (int ks = 0; ks < 4; ks++) {
            uint32_t bb[2];
            bb[0] = *(const uint32_t*)&rb[lr * RS_RPITCH + ks * 16 + 2 * t];
            bb[1] = *(const uint32_t*)&rb[lr * RS_RPITCH + ks * 16 + 2 * t + 8];
            mma_f16(c, afrag[ks], bb);
        }
        const int kc = ch * RS_CROWS + lrb + 2 * t;
        float2 o0 = *(float2*)&sscores[g * SC_PITCH + kc];
        o0.x += c[0]; o0.y += c[1];
        *(float2*)&sscores[g * SC_PITCH + kc] = o0;
        if (g < 4) {
            float2 o1 = *(float2*)&sscores[(g + 8) * SC_PITCH + kc];
            o1.x += c[2]; o1.y += c[3];
            *(float2*)&sscores[(g + 8) * SC_PITCH + kc] = o1;
        }
    }
    __syncthreads();

    softmax_epilogue(sscores, smask, probs, s, wid, lane);
}

// ---------------- split-K reduce + bias + residual + LayerNorm ----------------
template<int NPART, int F32OUT>
__global__ void __launch_bounds__(256) ln_red_kernel(
    const float* __restrict__ part, const float* __restrict__ bias,
    const __half* __restrict__ res,
    const float* __restrict__ g, const float* __restrict__ b, void* __restrict__ outv)
{
    const int s = blockIdx.x;
    const int tid = threadIdx.x;
    const int lane = tid & 31, wid = tid >> 5;
    __shared__ float red[8];

    float v[3];
    float lsum = 0.f;
#pragma unroll
    for (int i = 0; i < 3; i++) {
        const int idx = tid + i * 256;
        float acc = bias[idx] + __half2float(res[s * 768 + idx]);
#pragma unroll
        for (int p = 0; p < NPART; p++)
            acc += part[(long long)p * (SEQ * DM) + s * 768 + idx];
        v[i] = acc;
        lsum += acc;
    }
    lsum = warpRedSum(lsum);
    if (lane == 0) red[wid] = lsum;
    __syncthreads();
    float tot = 0.f;
#pragma unroll
    for (int i = 0; i < 8; i++) tot += red[i];
    const float mu = tot * (1.0f / 768.0f);
    __syncthreads();

    float ls2 = 0.f;
#pragma unroll
    for (int i = 0; i < 3; i++) { const float d = v[i] - mu; ls2 += d * d; }
    ls2 = warpRedSum(ls2);
    if (lane == 0) red[wid] = ls2;
    __syncthreads();
    float tot2 = 0.f;
#pragma unroll
    for (int i = 0; i < 8; i++) tot2 += red[i];
    const float rs = rsqrtf(tot2 * (1.0f / 768.0f) + 1e-12f);

#pragma unroll
    for (int i = 0; i < 3; i++) {
        const int idx = tid + i * 256;
        const float o = (v[i] - mu) * rs * g[idx] + b[idx];
        if (F32OUT) ((float*)outv)[s * 768 + idx] = o;
        else        ((__half*)outv)[s * 768 + idx] = __float2half(o);
    }
}

// ---------------- launcher ----------------
extern "C" void kernel_launch(void* const* d_in, const int* in_sizes, int n_in,
                              void* d_out, int out_size)
{
    const float* hid  = (const float*)d_in[0];
    const float* mask = (const float*)d_in[1];
    const float* rel  = (const float*)d_in[2];
    const float* rel2 = (const float*)d_in[3];
    const float* rela = (const float*)d_in[4];
    const float* Wq = (const float*)d_in[5];   const float* bq = (const float*)d_in[6];
    const float* Wk = (const float*)d_in[7];   const float* bk = (const float*)d_in[8];
    const float* Wv = (const float*)d_in[9];   const float* bv = (const float*)d_in[10];
    const float* Wo = (const float*)d_in[11];  const float* bo = (const float*)d_in[12];
    const float* g1 = (const float*)d_in[13];  const float* b1 = (const float*)d_in[14];
    const float* Wi = (const float*)d_in[15];  const float* bi = (const float*)d_in[16];
    const float* W2 = (const float*)d_in[17];  const float* b2 = (const float*)d_in[18];
    const float* g2 = (const float*)d_in[19];  const float* b2g = (const float*)d_in[20];

    __half *relsum, *probs, *h16, *hbuf, *q, *k, *vt, *ctx, *attn, *inter;
    __half *wq16, *wk16, *wv16, *wo16, *wi16, *w216;
    float *scores, *part;
    cudaGetSymbolAddress((void**)&relsum, g_relsum);
    cudaGetSymbolAddress((void**)&scores, g_scores);
    cudaGetSymbolAddress((void**)&probs, g_probs);
    cudaGetSymbolAddress((void**)&part, g_part);
    cudaGetSymbolAddress((void**)&h16, g_h16);
    cudaGetSymbolAddress((void**)&hbuf, g_hbuf);
    cudaGetSymbolAddress((void**)&q, g_q);
    cudaGetSymbolAddress((void**)&k, g_k);
    cudaGetSymbolAddress((void**)&vt, g_vt);
    cudaGetSymbolAddress((void**)&ctx, g_ctx);
    cudaGetSymbolAddress((void**)&attn, g_attn);
    cudaGetSymbolAddress((void**)&inter, g_inter);
    cudaGetSymbolAddress((void**)&wq16, g_wq16);
    cudaGetSymbolAddress((void**)&wk16, g_wk16);
    cudaGetSymbolAddress((void**)&wv16, g_wv16);
    cudaGetSymbolAddress((void**)&wo16, g_wo16);
    cudaGetSymbolAddress((void**)&wi16, g_wi16);
    cudaGetSymbolAddress((void**)&w216, g_w216);

    cudaFuncSetAttribute(hgemm_g<0, 0>, cudaFuncAttributeMaxDynamicSharedMemorySize, GEMM_SMEM);
    cudaFuncSetAttribute(hgemm_g<0, 1>, cudaFuncAttributeMaxDynamicSharedMemorySize, GEMM_SMEM);
    cudaFuncSetAttribute(hgemm_g<1, 0>, cudaFuncAttributeMaxDynamicSharedMemorySize, GEMM_SMEM);
    cudaFuncSetAttribute(hgemm_sk, cudaFuncAttributeMaxDynamicSharedMemorySize, GEMM_SMEM);
    cudaFuncSetAttribute(hqkv_kernel, cudaFuncAttributeMaxDynamicSharedMemorySize, GEMM_SMEM);
    cudaFuncSetAttribute(hgemm_pv, cudaFuncAttributeMaxDynamicSharedMemorySize, GEMM_SMEM64);
    cudaFuncSetAttribute(rel_softmax_kernel, cudaFuncAttributeMaxDynamicSharedMemorySize, RS_SMEM);
    cudaFuncSetAttribute(rs0_kernel, cudaFuncAttributeMaxDynamicSharedMemorySize, RS0_SMEM);

    // side stream + events (created once; reused; graph fork/join pattern)
    static cudaStream_t s_side = nullptr;
    static cudaEvent_t ev_fork = nullptr, ev_join = nullptr;
    if (s_side == nullptr) {
        cudaStreamCreateWithFlags(&s_side, cudaStreamNonBlocking);
        cudaEventCreateWithFlags(&ev_fork, cudaEventDisableTiming);
        cudaEventCreateWithFlags(&ev_join, cudaEventDisableTiming);
    }

    // fork: FFN weight conversion on side stream (hidden under layer-0 qkv/qk/rs0)
    cudaEventRecord(ev_fork, 0);
    cudaStreamWaitEvent(s_side, ev_fork, 0);
    f2h2_kernel<<<dim3(NLAYERS * DFF * DM / 4 / 256, 1, 2), 256, 0, s_side>>>(
        (const float4*)Wi, (const float4*)W2, (uint2*)wi16, (uint2*)w216);
    cudaEventRecord(ev_join, s_side);

    // main: hidden + attention weights (needed immediately by layer-0 qkv)
    f2h1_kernel<<<SEQ * DM / 4 / 256, 256>>>((const float4*)hid, (uint2*)h16);
    f2h4_kernel<<<dim3(NLAYERS * DM * DM / 4 / 256, 1, 4), 256>>>(
        (const float4*)Wq, (const float4*)Wk, (const float4*)Wv, (const float4*)Wo,
        (uint2*)wq16, (uint2*)wk16, (uint2*)wv16, (uint2*)wo16);

    const __half* h = h16;
    for (int l = 0; l < NLAYERS; l++) {
        const size_t wofs  = (size_t)l * DM * DM;
        const size_t wiofs = (size_t)l * DFF * DM;

        // fused Q/K/V projections (128x128 tiles)
        hqkv_kernel<<<dim3(6, 8, 3), 256, GEMM_SMEM>>>(
            h, wq16 + wofs, wk16 + wofs, wv16 + wofs,
            bq + l * 768, bk + l * 768, bv + l * 768, q, k, vt);

        // logits = q @ k^T (fp32 out)
        hgemm_g<0, 1><<<dim3(8, 8, 12), 256, GEMM_SMEM>>>(
            q, k, nullptr, scores, 64, 1024, 65536LL, 65536LL, 1048576LL);

        // + rel term + mask + softmax -> fp16 probs
        if (l == 0) {
            rs0_kernel<<<1024, 256, RS0_SMEM>>>(
                (const float4*)rel, (const float4*)rel2, (const float4*)rela,
                (uint2*)relsum, q, scores, probs, mask);
        } else {
            rel_softmax_kernel<<<1024, 256, RS_SMEM>>>(relsum, q, scores, probs, mask);
        }

        // ctx = probs @ v  (split-K=4)
        hgemm_pv<<<dim3(4, 8, 12), 256, GEMM_SMEM64>>>(probs, vt, part);
        pv_reduce<<<768, 256>>>((const float4*)part, (uint2*)ctx);

        // output projection: split-K=2, reduce+bias+residual+LN fused
        hgemm_sk<<<dim3(6, 8, 2), 256, GEMM_SMEM>>>(ctx, wo16 + wofs, part, 768, 384);
        ln_red_kernel<2, 0><<<1024, 256>>>(part, bo + l * 768, h,
                                           g1 + l * 768, b1 + l * 768, attn);

        // join FFN-weight conversion before first use
        if (l == 0) cudaStreamWaitEvent(0, ev_join, 0);

        // FFN
        hgemm_g<1, 0><<<dim3(24, 8, 1), 256, GEMM_SMEM>>>(
            attn, wi16 + wiofs, bi + l * 3072, inter, 768, 3072, 0, 0, 0);

        // FFN2: split-K=4, reduce+bias+residual+LN fused
        hgemm_sk<<<dim3(6, 8, 4), 256, GEMM_SMEM>>>(inter, w216 + wiofs, part, 3072, 768);
        if (l == NLAYERS - 1) {
            ln_red_kernel<4, 1><<<1024, 256>>>(part, b2 + l * 768, attn,
                                               g2 + l * 768, b2g + l * 768, d_out);
        } else {
            ln_red_kernel<4, 0><<<1024, 256>>>(part, b2 + l * 768, attn,
                                               g2 + l * 768, b2g + l * 768, hbuf);
        }
        h = hbuf;
    }
}

// round 14
// speedup vs baseline: 1.0492x; 1.0492x over previous
#include <cuda_runtime.h>
#include <cuda_fp16.h>
#include <math.h>
#include <stdint.h>

#define SEQ 1024
#define DM  768
#define NHEAD 12
#define HDIM 64
#define NLAYERS 4
#define DFF 3072

// ---------------- scratch (static device memory; no runtime allocs) ----------------
__device__ __half g_relsum[(size_t)SEQ * SEQ * HDIM];         // 128 MB (fp16)
__device__ float  g_scores[(size_t)NHEAD * SEQ * SEQ];        // 48 MB (fp32 logits)
__device__ __half g_probs[(size_t)NHEAD * SEQ * SEQ];         // 24 MB (fp16 probs)
__device__ float  g_part[4 * SEQ * DM];                       // split-K partials
__device__ __half g_h16[SEQ * DM];
__device__ __half g_hbuf[SEQ * DM];
__device__ __half g_q[NHEAD * SEQ * HDIM];
__device__ __half g_k[NHEAD * SEQ * HDIM];
__device__ __half g_vt[NHEAD * HDIM * SEQ];
__device__ __half g_ctx[SEQ * DM];
__device__ __half g_attn[SEQ * DM];
__device__ __half g_inter[SEQ * DFF];
// fp16 weights (converted once per launch)
__device__ __half g_wq16[NLAYERS * DM * DM];
__device__ __half g_wk16[NLAYERS * DM * DM];
__device__ __half g_wv16[NLAYERS * DM * DM];
__device__ __half g_wo16[NLAYERS * DM * DM];
__device__ __half g_wi16[NLAYERS * DFF * DM];
__device__ __half g_w216[NLAYERS * DM * DFF];

// ---------------- helpers ----------------
__device__ __forceinline__ float warpRedMax(float v) {
#pragma unroll
    for (int o = 16; o > 0; o >>= 1) v = fmaxf(v, __shfl_xor_sync(0xffffffffu, v, o));
    return v;
}
__device__ __forceinline__ float warpRedSum(float v) {
#pragma unroll
    for (int o = 16; o > 0; o >>= 1) v += __shfl_xor_sync(0xffffffffu, v, o);
    return v;
}
__device__ __forceinline__ void cp16(uint32_t dst, const void* src) {
    asm volatile("cp.async.cg.shared.global [%0], [%1], 16;" :: "r"(dst), "l"(src));
}
__device__ __forceinline__ void mma_f16(float* c, const uint32_t* a, const uint32_t* b) {
    asm volatile(
        "mma.sync.aligned.m16n8k16.row.col.f32.f16.f16.f32 "
        "{%0,%1,%2,%3}, {%4,%5,%6,%7}, {%8,%9}, {%0,%1,%2,%3};"
        : "+f"(c[0]), "+f"(c[1]), "+f"(c[2]), "+f"(c[3])
        : "r"(a[0]), "r"(a[1]), "r"(a[2]), "r"(a[3]), "r"(b[0]), "r"(b[1]));
}
__device__ __forceinline__ void ldsm_x4(uint32_t& r0, uint32_t& r1, uint32_t& r2, uint32_t& r3,
                                        uint32_t addr) {
    asm volatile("ldmatrix.sync.aligned.m8n8.x4.shared.b16 {%0,%1,%2,%3}, [%4];"
                 : "=r"(r0), "=r"(r1), "=r"(r2), "=r"(r3) : "r"(addr));
}
__device__ __forceinline__ uint2 f4_to_h4(float4 x) {
    __half2 h0 = __floats2half2_rn(x.x, x.y);
    __half2 h1 = __floats2half2_rn(x.z, x.w);
    uint2 o; o.x = *(uint32_t*)&h0; o.y = *(uint32_t*)&h1;
    return o;
}

// ---------------- one-shot fp32 -> fp16 conversions ----------------
__global__ void __launch_bounds__(256) f2h1_kernel(
    const float4* __restrict__ s, uint2* __restrict__ d)
{
    const int i = blockIdx.x * 256 + threadIdx.x;
    d[i] = f4_to_h4(s[i]);
}
__global__ void __launch_bounds__(256) f2h4_kernel(
    const float4* __restrict__ s0, const float4* __restrict__ s1,
    const float4* __restrict__ s2, const float4* __restrict__ s3,
    uint2* __restrict__ d0, uint2* __restrict__ d1,
    uint2* __restrict__ d2, uint2* __restrict__ d3)
{
    const int i = blockIdx.x * 256 + threadIdx.x;
    const int z = blockIdx.z;
    const float4* s = (z == 0) ? s0 : (z == 1) ? s1 : (z == 2) ? s2 : s3;
    uint2* d        = (z == 0) ? d0 : (z == 1) ? d1 : (z == 2) ? d2 : d3;
    d[i] = f4_to_h4(s[i]);
}
__global__ void __launch_bounds__(256) f2h2_kernel(
    const float4* __restrict__ s0, const float4* __restrict__ s1,
    uint2* __restrict__ d0, uint2* __restrict__ d1)
{
    const int i = blockIdx.x * 256 + threadIdx.x;
    const float4* s = blockIdx.z ? s1 : s0;
    uint2* d        = blockIdx.z ? d1 : d0;
    d[i] = f4_to_h4(s[i]);
}

// ---------------- 128x64 fp16 GEMM mainloop (256 threads, ldmatrix, 3-stage) ----------------
#define A_ST 9216    // halves per A stage
#define W_ST 4608    // halves per W stage
#define GEMM_SMEM ((3 * A_ST + 3 * W_ST) * 2)   // 82944 B

__device__ __forceinline__ void hgemm_mainloop(
    const __half* __restrict__ Ag, const __half* __restrict__ Wg,
    __half* __restrict__ sm, int Kloop, int lda, int ldw, float acc[2][4][4])
{
    const int tid = threadIdx.x;
    const int srow = tid >> 3;
    const int scol = (tid & 7) << 3;

    __half* As = sm;
    __half* Ws = sm + 3 * A_ST;

    const uint32_t asB = (uint32_t)__cvta_generic_to_shared(As);
    const uint32_t wsB = (uint32_t)__cvta_generic_to_shared(Ws);
    const uint32_t sa0 = asB + (uint32_t)(srow * 72 + scol) * 2u;
    const uint32_t sw0 = wsB + (uint32_t)(srow * 72 + scol) * 2u;

    const __half* Agp = Ag + (long long)srow * lda + scol;
    const __half* Wgp = Wg + (long long)srow * ldw + scol;

    const int KT = Kloop >> 6;

#pragma unroll
    for (int st = 0; st < 2; st++) {
        if (st < KT) {
#pragma unroll
            for (int p = 0; p < 4; p++)
                cp16(sa0 + (uint32_t)(st * A_ST + p * 32 * 72) * 2u, Agp + (long long)(p * 32) * lda + st * 64);
#pragma unroll
            for (int p = 0; p < 2; p++)
                cp16(sw0 + (uint32_t)(st * W_ST + p * 32 * 72) * 2u, Wgp + (long long)(p * 32) * ldw + st * 64);
        }
        asm volatile("cp.async.commit_group;");
    }

    const int wid = tid >> 5, lane = tid & 31;
    const int wm = wid & 3, wn = wid >> 2;
    const int a_row = wm * 32 + (lane & 15);
    const int a_ko  = (lane >> 4) << 3;
    const int b_row = wn * 32 + (lane & 7) + ((lane >> 4) << 3);
    const int b_ko  = ((lane >> 3) & 1) << 3;

    const uint32_t aF = asB + (uint32_t)(a_row * 72 + a_ko) * 2u;
    const uint32_t wF = wsB + (uint32_t)(b_row * 72 + b_ko) * 2u;

    for (int kt = 0; kt < KT; kt++) {
        asm volatile("cp.async.wait_group 1;");
        __syncthreads();

        const int pf = kt + 2;
        if (pf < KT) {
            const int st = pf % 3;
#pragma unroll
            for (int p = 0; p < 4; p++)
                cp16(sa0 + (uint32_t)(st * A_ST + p * 32 * 72) * 2u, Agp + (long long)(p * 32) * lda + pf * 64);
#pragma unroll
            for (int p = 0; p < 2; p++)
                cp16(sw0 + (uint32_t)(st * W_ST + p * 32 * 72) * 2u, Wgp + (long long)(p * 32) * ldw + pf * 64);
        }
        asm volatile("cp.async.commit_group;");

        const uint32_t aS = aF + (uint32_t)((kt % 3) * A_ST) * 2u;
        const uint32_t wS = wF + (uint32_t)((kt % 3) * W_ST) * 2u;

#pragma unroll
        for (int ks = 0; ks < 4; ks++) {
            uint32_t a[2][4], b[2][4];
#pragma unroll
            for (int mt = 0; mt < 2; mt++)
                ldsm_x4(a[mt][0], a[mt][1], a[mt][2], a[mt][3],
                        aS + (uint32_t)(mt * 16 * 72 + ks * 16) * 2u);
#pragma unroll
            for (int nt2 = 0; nt2 < 2; nt2++)
                ldsm_x4(b[nt2][0], b[nt2][1], b[nt2][2], b[nt2][3],
                        wS + (uint32_t)(nt2 * 16 * 72 + ks * 16) * 2u);
#pragma unroll
            for (int mt = 0; mt < 2; mt++)
#pragma unroll
                for (int nt = 0; nt < 4; nt++) {
                    uint32_t bb[2] = { b[nt >> 1][(nt & 1) * 2], b[nt >> 1][(nt & 1) * 2 + 1] };
                    mma_f16(acc[mt][nt], a[mt], bb);
                }
        }
    }
}

// ---------------- generic fp16 GEMM (z-batched): C = A @ W^T (+bias, GELU) ----------------
template<int EPI, int F32OUT>
__global__ void __launch_bounds__(256, 2) hgemm_g(
    const __half* __restrict__ A, const __half* __restrict__ W,
    const float* __restrict__ bias, void* __restrict__ Cv,
    int K, int ldC, long long sA, long long sW, long long sC)
{
    extern __shared__ __half smh[];
    const int bz = blockIdx.z;
    const int m0 = blockIdx.y << 7, n0 = blockIdx.x << 6;

    float acc[2][4][4];
#pragma unroll
    for (int i = 0; i < 2; i++)
#pragma unroll
        for (int j = 0; j < 4; j++)
#pragma unroll
            for (int l = 0; l < 4; l++) acc[i][j][l] = 0.f;

    hgemm_mainloop(A + sA * bz + (long long)m0 * K,
                   W + sW * bz + (long long)n0 * K, smh, K, K, K, acc);

    const int tid = threadIdx.x, wid = tid >> 5, lane = tid & 31;
    const int wm = wid & 3, wn = wid >> 2, g = lane >> 2, t = lane & 3;

#pragma unroll
    for (int mt = 0; mt < 2; mt++) {
        const int rb = m0 + wm * 32 + mt * 16 + g;
#pragma unroll
        for (int nt = 0; nt < 4; nt++) {
            const int cb = n0 + wn * 32 + nt * 8 + 2 * t;
#pragma unroll
            for (int hf = 0; hf < 2; hf++) {
                const int m = rb + hf * 8;
                float v0 = acc[mt][nt][hf * 2 + 0];
                float v1 = acc[mt][nt][hf * 2 + 1];
                if (bias) { v0 += bias[cb]; v1 += bias[cb + 1]; }
                if (EPI == 1) {
                    v0 = 0.5f * v0 * (1.0f + erff(v0 * 0.70710678118654752f));
                    v1 = 0.5f * v1 * (1.0f + erff(v1 * 0.70710678118654752f));
                }
                if (F32OUT) {
                    float* C = (float*)Cv + sC * bz;
                    *(float2*)&C[(long long)m * ldC + cb] = make_float2(v0, v1);
                } else {
                    __half* C = (__half*)Cv + sC * bz;
                    __half2 h2 = __floats2half2_rn(v0, v1);
                    *(__half2*)&C[(long long)m * ldC + cb] = h2;
                }
            }
        }
    }
}

// ---------------- split-K GEMM: part[ks] = A[:, ks*Ksplit:+Ksplit] @ W[:, same]^T ----------------
__global__ void __launch_bounds__(256, 2) hgemm_sk(
    const __half* __restrict__ A, const __half* __restrict__ W,
    float* __restrict__ part, int Kfull, int Ksplit)
{
    extern __shared__ __half smh[];
    const int ks = blockIdx.z;
    const int m0 = blockIdx.y << 7, n0 = blockIdx.x << 6;

    float acc[2][4][4];
#pragma unroll
    for (int i = 0; i < 2; i++)
#pragma unroll
        for (int j = 0; j < 4; j++)
#pragma unroll
            for (int l = 0; l < 4; l++) acc[i][j][l] = 0.f;

    hgemm_mainloop(A + (long long)m0 * Kfull + (long long)ks * Ksplit,
                   W + (long long)n0 * Kfull + (long long)ks * Ksplit,
                   smh, Ksplit, Kfull, Kfull, acc);

    float* C = part + (long long)ks * (SEQ * DM);

    const int tid = threadIdx.x, wid = tid >> 5, lane = tid & 31;
    const int wm = wid & 3, wn = wid >> 2, g = lane >> 2, t = lane & 3;

#pragma unroll
    for (int mt = 0; mt < 2; mt++) {
        const int rb = m0 + wm * 32 + mt * 16 + g;
#pragma unroll
        for (int nt = 0; nt < 4; nt++) {
            const int cb = n0 + wn * 32 + nt * 8 + 2 * t;
#pragma unroll
            for (int hf = 0; hf < 2; hf++) {
                const int m = rb + hf * 8;
                *(float2*)&C[(long long)m * DM + cb] =
                    make_float2(acc[mt][nt][hf * 2 + 0], acc[mt][nt][hf * 2 + 1]);
            }
        }
    }
}

// ---------------- fused QKV projection (fp16) ----------------
__global__ void __launch_bounds__(256, 2) hqkv_kernel(
    const __half* __restrict__ h,
    const __half* __restrict__ Wq, const __half* __restrict__ Wk, const __half* __restrict__ Wv,
    const float* __restrict__ bq, const float* __restrict__ bk, const float* __restrict__ bv,
    __half* __restrict__ qo, __half* __restrict__ ko, __half* __restrict__ vto)
{
    extern __shared__ __half smh[];
    const int z = blockIdx.z;
    const __half* W   = (z == 0) ? Wq : (z == 1) ? Wk : Wv;
    const float* bias = (z == 0) ? bq : (z == 1) ? bk : bv;
    __half* out       = (z == 0) ? qo : (z == 1) ? ko : vto;
    const float scale = (z == 0) ? 0.125f : 1.0f;
    const int m0 = blockIdx.y << 7, n0 = blockIdx.x << 6;

    float acc[2][4][4];
#pragma unroll
    for (int i = 0; i < 2; i++)
#pragma unroll
        for (int j = 0; j < 4; j++)
#pragma unroll
            for (int l = 0; l < 4; l++) acc[i][j][l] = 0.f;

    hgemm_mainloop(h + (long long)m0 * DM, W + (long long)n0 * DM, smh, DM, DM, DM, acc);

    const int tid = threadIdx.x, wid = tid >> 5, lane = tid & 31;
    const int wm = wid & 3, wn = wid >> 2, g = lane >> 2, t = lane & 3;

#pragma unroll
    for (int mt = 0; mt < 2; mt++) {
        const int rb = m0 + wm * 32 + mt * 16 + g;
#pragma unroll
        for (int nt = 0; nt < 4; nt++) {
            const int cb = n0 + wn * 32 + nt * 8 + 2 * t;
#pragma unroll
            for (int hf = 0; hf < 2; hf++) {
                const int m = rb + hf * 8;
                float v0 = (acc[mt][nt][hf * 2 + 0] + bias[cb]) * scale;
                float v1 = (acc[mt][nt][hf * 2 + 1] + bias[cb + 1]) * scale;
                if (z < 2) {
                    const long long idx = ((long long)(cb >> 6) << 16) + (long long)m * 64 + (cb & 63);
                    __half2 h2 = __floats2half2_rn(v0, v1);
                    *(__half2*)&out[idx] = h2;
                } else {
                    out[(long long)cb * 1024 + m]       = __float2half(v0);
                    out[(long long)(cb + 1) * 1024 + m] = __float2half(v1);
                }
            }
        }
    }
}

// ---------------- PV split-K GEMM (split-K=2; fp16 probs x fp16 vt -> fp32 partials) ----------------
__global__ void __launch_bounds__(256, 2) hgemm_pv(
    const __half* __restrict__ probs, const __half* __restrict__ vt, float* __restrict__ part)
{
    extern __shared__ __half smh[];
    const int ks = blockIdx.x;           // 0..1
    const int m0 = blockIdx.y << 7;
    const int hd = blockIdx.z;

    float acc[2][4][4];
#pragma unroll
    for (int i = 0; i < 2; i++)
#pragma unroll
        for (int j = 0; j < 4; j++)
#pragma unroll
            for (int l = 0; l < 4; l++) acc[i][j][l] = 0.f;

    hgemm_mainloop(probs + (long long)hd * 1048576 + (long long)m0 * 1024 + ks * 512,
                   vt + (long long)hd * 65536 + ks * 512,
                   smh, 512, 1024, 1024, acc);

    float* C = part + (long long)ks * 786432 + hd * 64;

    const int tid = threadIdx.x, wid = tid >> 5, lane = tid & 31;
    const int wm = wid & 3, wn = wid >> 2, g = lane >> 2, t = lane & 3;

#pragma unroll
    for (int mt = 0; mt < 2; mt++) {
        const int rb = m0 + wm * 32 + mt * 16 + g;
#pragma unroll
        for (int nt = 0; nt < 4; nt++) {
            const int cb = wn * 32 + nt * 8 + 2 * t;
#pragma unroll
            for (int hf = 0; hf < 2; hf++) {
                const int m = rb + hf * 8;
                *(float2*)&C[(long long)m * 768 + cb] =
                    make_float2(acc[mt][nt][hf * 2 + 0], acc[mt][nt][hf * 2 + 1]);
            }
        }
    }
}

// ---------------- PV reduce: ctx(fp16) = sum of 2 fp32 partials ----------------
__global__ void __launch_bounds__(256) pv_reduce(
    const float4* __restrict__ part, uint2* __restrict__ ctx)
{
    const int i = blockIdx.x * 256 + threadIdx.x;
    float4 a = part[i];
    const float4 b = part[i + 196608];
    a.x += b.x; a.y += b.y; a.z += b.z; a.w += b.w;
    ctx[i] = f4_to_h4(a);
}

// ---------------- shared softmax epilogue (warp-parallel) ----------------
#define SC_PITCH 1032
#define RS_QPITCH 72
#define RS_RPITCH 72

__device__ __forceinline__ void softmax_epilogue(
    const float* __restrict__ sscores, const float* __restrict__ smask,
    __half* __restrict__ probs, int s, int wid, int lane)
{
#pragma unroll
    for (int hh = 0; hh < 2; hh++) {
        if (hh == 1 && wid >= 4) break;
        const int n = hh ? (8 + wid) : wid;

        float4 v[8];
        float m = -1e30f;
#pragma unroll
        for (int j = 0; j < 8; j++) {
            const int c4 = (lane + 32 * j) << 2;
            float4 a = *(const float4*)&sscores[n * SC_PITCH + c4];
            const float4 mk = *(const float4*)&smask[c4];
            a.x += mk.x; a.y += mk.y; a.z += mk.z; a.w += mk.w;
            v[j] = a;
            m = fmaxf(m, fmaxf(fmaxf(a.x, a.y), fmaxf(a.z, a.w)));
        }
        m = warpRedMax(m);

        float sum = 0.f;
#pragma unroll
        for (int j = 0; j < 8; j++) {
            v[j].x = __expf(v[j].x - m); v[j].y = __expf(v[j].y - m);
            v[j].z = __expf(v[j].z - m); v[j].w = __expf(v[j].w - m);
            sum += v[j].x + v[j].y + v[j].z + v[j].w;
        }
        sum = warpRedSum(sum);
        const float inv = 1.0f / sum;

        __half* prow = probs + (((long long)n << 10) + s) * 1024;
#pragma unroll
        for (int j = 0; j < 8; j++) {
            const int c4 = (lane + 32 * j) << 2;
            __half2 p0 = __floats2half2_rn(v[j].x * inv, v[j].y * inv);
            __half2 p1 = __floats2half2_rn(v[j].z * inv, v[j].w * inv);
            uint2 o; o.x = *(uint32_t*)&p0; o.y = *(uint32_t*)&p1;
            *(uint2*)&prow[c4] = o;
        }
    }
}

// ---------------- layer-0 fused: relsum build + rel-score + mask + softmax ----------------
#define RS0_SMEM 74368

__global__ void __launch_bounds__(256) rs0_kernel(
    const float4* __restrict__ r0, const float4* __restrict__ r1,
    const float4* __restrict__ r2, uint2* __restrict__ rsum,
    const __half* __restrict__ qb, const float* __restrict__ scores,
    __half* __restrict__ probs, const float* __restrict__ mask)
{
    extern __shared__ char smc[];
    __half* qs      = (__half*)smc;
    float*  sscores = (float*)(smc + 2304);
    float*  smask   = (float*)(smc + 51840);
    __half* relb    = (__half*)(smc + 55936);

    const int s = blockIdx.x;
    const int tid = threadIdx.x;
    const int wid = tid >> 5, lane = tid & 31;
    const int g = lane >> 2, t = lane & 3;

    {
        const uint32_t ss_s = (uint32_t)__cvta_generic_to_shared(sscores);
#pragma unroll
        for (int p = 0; p < 12; p++) {
            const int idx = tid + 256 * p;
            const int n = idx >> 8, c4 = (idx & 255) << 2;
            cp16(ss_s + (uint32_t)(n * SC_PITCH + c4) * 4u,
                 scores + (((long long)n << 10) + s) * 1024 + c4);
        }
        cp16((uint32_t)__cvta_generic_to_shared(smask) + (uint32_t)(tid << 4),
             mask + (tid << 2));
        asm volatile("cp.async.commit_group;");
    }

    for (int i = tid; i < 16 * 64; i += 256) {
        const int r = i >> 6, c = i & 63;
        qs[r * RS_QPITCH + c] = (r < 12) ? qb[((long long)r << 16) + (s << 6) + c] : __float2half(0.f);
    }

    const long long base = ((long long)s << 14);
    float4 ra[4], rb4[4], rc[4];
#pragma unroll
    for (int p = 0; p < 4; p++) {
        const long long idx = base + tid + 256 * p;
        ra[p] = r0[idx]; rb4[p] = r1[idx]; rc[p] = r2[idx];
    }

    asm volatile("cp.async.wait_group 0;");
    __syncthreads();

    uint32_t afrag[4][4];
#pragma unroll
    for (int ks = 0; ks < 4; ks++) {
        afrag[ks][0] = *(const uint32_t*)&qs[g * RS_QPITCH + ks * 16 + 2 * t];
        afrag[ks][1] = *(const uint32_t*)&qs[(g + 8) * RS_QPITCH + ks * 16 + 2 * t];
        afrag[ks][2] = *(const uint32_t*)&qs[g * RS_QPITCH + ks * 16 + 2 * t + 8];
        afrag[ks][3] = *(const uint32_t*)&qs[(g + 8) * RS_QPITCH + ks * 16 + 2 * t + 8];
    }

    const int lrb = wid * 8;
    const int lr  = lrb + g;

    for (int ch = 0; ch < 16; ch++) {
        __half* rbuf = relb + (ch & 1) * (64 * RS_RPITCH);
#pragma unroll
        for (int p = 0; p < 4; p++) {
            float4 x = ra[p];
            x.x += rb4[p].x + rc[p].x; x.y += rb4[p].y + rc[p].y;
            x.z += rb4[p].z + rc[p].z; x.w += rb4[p].w + rc[p].w;
            const uint2 hv = f4_to_h4(x);
            const int il = tid + 256 * p;
            const int r = il >> 4, c4 = (il & 15) << 2;
            *(uint2*)&rbuf[r * RS_RPITCH + c4] = hv;
            rsum[base + (long long)ch * 1024 + il] = hv;
        }
        __syncthreads();

        if (ch + 1 < 16) {
#pragma unroll
            for (int p = 0; p < 4; p++) {
                const long long idx = base + (long long)(ch + 1) * 1024 + tid + 256 * p;
                ra[p] = r0[idx]; rb4[p] = r1[idx]; rc[p] = r2[idx];
            }
        }

        float c[4] = {0.f, 0.f, 0.f, 0.f};
#pragma unroll
        for (int ks = 0; ks < 4; ks++) {
            uint32_t bb[2];
            bb[0] = *(const uint32_t*)&rbuf[lr * RS_RPITCH + ks * 16 + 2 * t];
            bb[1] = *(const uint32_t*)&rbuf[lr * RS_RPITCH + ks * 16 + 2 * t + 8];
            mma_f16(c, afrag[ks], bb);
        }
        const int kc = ch * 64 + lrb + 2 * t;
        float2 o0 = *(float2*)&sscores[g * SC_PITCH + kc];
        o0.x += c[0]; o0.y += c[1];
        *(float2*)&sscores[g * SC_PITCH + kc] = o0;
        if (g < 4) {
            float2 o1 = *(float2*)&sscores[(g + 8) * SC_PITCH + kc];
            o1.x += c[2]; o1.y += c[3];
            *(float2*)&sscores[(g + 8) * SC_PITCH + kc] = o1;
        }
    }
    __syncthreads();

    softmax_epilogue(sscores, smask, probs, s, wid, lane);
}

// ---------------- layers 1-3: rel-score + mask + softmax ----------------
#define RS_CROWS 64
#define RS_CHUNK_H (RS_CROWS * RS_RPITCH)
#define RS_NBUF 6
#define RS_NCHUNK 16
#define RS_SMEM 111232

__global__ void __launch_bounds__(256) rel_softmax_kernel(
    const __half* __restrict__ rel, const __half* __restrict__ qb,
    const float* __restrict__ scores, __half* __restrict__ probs,
    const float* __restrict__ mask)
{
    extern __shared__ char smc[];
    __half* qs      = (__half*)smc;
    float*  sscores = (float*)(smc + 2304);
    float*  smask   = (float*)(smc + 51840);
    __half* relb    = (__half*)(smc + 55936);

    const int s = blockIdx.x;
    const int tid = threadIdx.x;
    const int wid = tid >> 5, lane = tid & 31;
    const int g = lane >> 2, t = lane & 3;

    {
        const uint32_t ss_s = (uint32_t)__cvta_generic_to_shared(sscores);
#pragma unroll
        for (int p = 0; p < 12; p++) {
            const int idx = tid + 256 * p;
            const int n = idx >> 8, c4 = (idx & 255) << 2;
            cp16(ss_s + (uint32_t)(n * SC_PITCH + c4) * 4u,
                 scores + (((long long)n << 10) + s) * 1024 + c4);
        }
        cp16((uint32_t)__cvta_generic_to_shared(smask) + (uint32_t)(tid << 4),
             mask + (tid << 2));
        asm volatile("cp.async.commit_group;");
    }

    for (int i = tid; i < 16 * 64; i += 256) {
        const int r = i >> 6, c = i & 63;
        qs[r * RS_QPITCH + c] = (r < 12) ? qb[((long long)r << 16) + (s << 6) + c] : __float2half(0.f);
    }

    const __half* relS = rel + ((long long)s << 16);
    const uint32_t relb_s = (uint32_t)__cvta_generic_to_shared(relb);

#pragma unroll
    for (int ch = 0; ch < RS_NBUF - 1; ch++) {
        const uint32_t dstb = relb_s + (uint32_t)(ch * RS_CHUNK_H) * 2u;
        const __half* src = relS + (long long)ch * RS_CROWS * 64;
#pragma unroll
        for (int p = 0; p < 2; p++) {
            const int idx = tid + 256 * p;
            const int r = idx >> 3, c8 = (idx & 7) << 3;
            cp16(dstb + (uint32_t)(r * RS_RPITCH + c8) * 2u, src + (long long)r * 64 + c8);
        }
        asm volatile("cp.async.commit_group;");
    }

    __syncthreads();

    uint32_t afrag[4][4];
#pragma unroll
    for (int ks = 0; ks < 4; ks++) {
        afrag[ks][0] = *(const uint32_t*)&qs[g * RS_QPITCH + ks * 16 + 2 * t];
        afrag[ks][1] = *(const uint32_t*)&qs[(g + 8) * RS_QPITCH + ks * 16 + 2 * t];
        afrag[ks][2] = *(const uint32_t*)&qs[g * RS_QPITCH + ks * 16 + 2 * t + 8];
        afrag[ks][3] = *(const uint32_t*)&qs[(g + 8) * RS_QPITCH + ks * 16 + 2 * t + 8];
    }

    const int lrb = wid * 8;
    const int lr  = lrb + g;

    for (int ch = 0; ch < RS_NCHUNK; ch++) {
        asm volatile("cp.async.wait_group 4;");
        __syncthreads();

        const int pf = ch + RS_NBUF - 1;
        if (pf < RS_NCHUNK) {
            const uint32_t dstb = relb_s + (uint32_t)((pf % RS_NBUF) * RS_CHUNK_H) * 2u;
            const __half* src = relS + (long long)pf * RS_CROWS * 64;
#pragma unroll
            for (int p = 0; p < 2; p++) {
                const int idx = tid + 256 * p;
                const int r = idx >> 3, c8 = (idx & 7) << 3;
                cp16(dstb + (uint32_t)(r * RS_RPITCH + c8) * 2u, src + (long long)r * 64 + c8);
            }
        }
        asm volatile("cp.async.commit_group;");

        const __half* rb = relb + (ch % RS_NBUF) * RS_CHUNK_H;
        float c[4] = {0.f, 0.f, 0.f, 0.f};
#pragma unroll
        for (int ks = 0; ks < 4; ks++) {
            uint32_t bb[2];
            bb[0] = *(const uint32_t*)&rb[lr * RS_RPITCH + ks * 16 + 2 * t];
            bb[1] = *(const uint32_t*)&rb[lr * RS_RPITCH + ks * 16 + 2 * t + 8];
            mma_f16(c, afrag[ks], bb);
        }
        const int kc = ch * RS_CROWS + lrb + 2 * t;
        float2 o0 = *(float2*)&sscores[g * SC_PITCH + kc];
        o0.x += c[0]; o0.y += c[1];
        *(float2*)&sscores[g * SC_PITCH + kc] = o0;
        if (g < 4) {
            float2 o1 = *(float2*)&sscores[(g + 8) * SC_PITCH + kc];
            o1.x += c[2]; o1.y += c[3];
            *(float2*)&sscores[(g + 8) * SC_PITCH + kc] = o1;
        }
    }
    __syncthreads();

    softmax_epilogue(sscores, smask, probs, s, wid, lane);
}

// ---------------- split-K reduce + bias + residual + LayerNorm ----------------
template<int NPART, int F32OUT>
__global__ void __launch_bounds__(256) ln_red_kernel(
    const float* __restrict__ part, const float* __restrict__ bias,
    const __half* __restrict__ res,
    const float* __restrict__ g, const float* __restrict__ b, void* __restrict__ outv)
{
    const int s = blockIdx.x;
    const int tid = threadIdx.x;
    const int lane = tid & 31, wid = tid >> 5;
    __shared__ float red[8];

    float v[3];
    float lsum = 0.f;
#pragma unroll
    for (int i = 0; i < 3; i++) {
        const int idx = tid + i * 256;
        float acc = bias[idx] + __half2float(res[s * 768 + idx]);
#pragma unroll
        for (int p = 0; p < NPART; p++)
            acc += part[(long long)p * (SEQ * DM) + s * 768 + idx];
        v[i] = acc;
        lsum += acc;
    }
    lsum = warpRedSum(lsum);
    if (lane == 0) red[wid] = lsum;
    __syncthreads();
    float tot = 0.f;
#pragma unroll
    for (int i = 0; i < 8; i++) tot += red[i];
    const float mu = tot * (1.0f / 768.0f);
    __syncthreads();

    float ls2 = 0.f;
#pragma unroll
    for (int i = 0; i < 3; i++) { const float d = v[i] - mu; ls2 += d * d; }
    ls2 = warpRedSum(ls2);
    if (lane == 0) red[wid] = ls2;
    __syncthreads();
    float tot2 = 0.f;
#pragma unroll
    for (int i = 0; i < 8; i++) tot2 += red[i];
    const float rs = rsqrtf(tot2 * (1.0f / 768.0f) + 1e-12f);

#pragma unroll
    for (int i = 0; i < 3; i++) {
        const int idx = tid + i * 256;
        const float o = (v[i] - mu) * rs * g[idx] + b[idx];
        if (F32OUT) ((float*)outv)[s * 768 + idx] = o;
        else        ((__half*)outv)[s * 768 + idx] = __float2half(o);
    }
}

// ---------------- launcher ----------------
extern "C" void kernel_launch(void* const* d_in, const int* in_sizes, int n_in,
                              void* d_out, int out_size)
{
    const float* hid  = (const float*)d_in[0];
    const float* mask = (const float*)d_in[1];
    const float* rel  = (const float*)d_in[2];
    const float* rel2 = (const float*)d_in[3];
    const float* rela = (const float*)d_in[4];
    const float* Wq = (const float*)d_in[5];   const float* bq = (const float*)d_in[6];
    const float* Wk = (const float*)d_in[7];   const float* bk = (const float*)d_in[8];
    const float* Wv = (const float*)d_in[9];   const float* bv = (const float*)d_in[10];
    const float* Wo = (const float*)d_in[11];  const float* bo = (const float*)d_in[12];
    const float* g1 = (const float*)d_in[13];  const float* b1 = (const float*)d_in[14];
    const float* Wi = (const float*)d_in[15];  const float* bi = (const float*)d_in[16];
    const float* W2 = (const float*)d_in[17];  const float* b2 = (const float*)d_in[18];
    const float* g2 = (const float*)d_in[19];  const float* b2g = (const float*)d_in[20];

    __half *relsum, *probs, *h16, *hbuf, *q, *k, *vt, *ctx, *attn, *inter;
    __half *wq16, *wk16, *wv16, *wo16, *wi16, *w216;
    float *scores, *part;
    cudaGetSymbolAddress((void**)&relsum, g_relsum);
    cudaGetSymbolAddress((void**)&scores, g_scores);
    cudaGetSymbolAddress((void**)&probs, g_probs);
    cudaGetSymbolAddress((void**)&part, g_part);
    cudaGetSymbolAddress((void**)&h16, g_h16);
    cudaGetSymbolAddress((void**)&hbuf, g_hbuf);
    cudaGetSymbolAddress((void**)&q, g_q);
    cudaGetSymbolAddress((void**)&k, g_k);
    cudaGetSymbolAddress((void**)&vt, g_vt);
    cudaGetSymbolAddress((void**)&ctx, g_ctx);
    cudaGetSymbolAddress((void**)&attn, g_attn);
    cudaGetSymbolAddress((void**)&inter, g_inter);
    cudaGetSymbolAddress((void**)&wq16, g_wq16);
    cudaGetSymbolAddress((void**)&wk16, g_wk16);
    cudaGetSymbolAddress((void**)&wv16, g_wv16);
    cudaGetSymbolAddress((void**)&wo16, g_wo16);
    cudaGetSymbolAddress((void**)&wi16, g_wi16);
    cudaGetSymbolAddress((void**)&w216, g_w216);

    cudaFuncSetAttribute(hgemm_g<0, 0>, cudaFuncAttributeMaxDynamicSharedMemorySize, GEMM_SMEM);
    cudaFuncSetAttribute(hgemm_g<0, 1>, cudaFuncAttributeMaxDynamicSharedMemorySize, GEMM_SMEM);
    cudaFuncSetAttribute(hgemm_g<1, 0>, cudaFuncAttributeMaxDynamicSharedMemorySize, GEMM_SMEM);
    cudaFuncSetAttribute(hgemm_sk, cudaFuncAttributeMaxDynamicSharedMemorySize, GEMM_SMEM);
    cudaFuncSetAttribute(hqkv_kernel, cudaFuncAttributeMaxDynamicSharedMemorySize, GEMM_SMEM);
    cudaFuncSetAttribute(hgemm_pv, cudaFuncAttributeMaxDynamicSharedMemorySize, GEMM_SMEM);
    cudaFuncSetAttribute(rel_softmax_kernel, cudaFuncAttributeMaxDynamicSharedMemorySize, RS_SMEM);
    cudaFuncSetAttribute(rs0_kernel, cudaFuncAttributeMaxDynamicSharedMemorySize, RS0_SMEM);

    // side stream + events (created once; reused; graph fork/join pattern)
    static cudaStream_t s_side = nullptr;
    static cudaEvent_t ev_fork = nullptr, ev_join = nullptr;
    if (s_side == nullptr) {
        cudaStreamCreateWithFlags(&s_side, cudaStreamNonBlocking);
        cudaEventCreateWithFlags(&ev_fork, cudaEventDisableTiming);
        cudaEventCreateWithFlags(&ev_join, cudaEventDisableTiming);
    }

    // fork: FFN weight conversion on side stream (hidden under layer-0 qkv/qk/rs0)
    cudaEventRecord(ev_fork, 0);
    cudaStreamWaitEvent(s_side, ev_fork, 0);
    f2h2_kernel<<<dim3(NLAYERS * DFF * DM / 4 / 256, 1, 2), 256, 0, s_side>>>(
        (const float4*)Wi, (const float4*)W2, (uint2*)wi16, (uint2*)w216);
    cudaEventRecord(ev_join, s_side);

    // main: hidden + attention weights (needed immediately by layer-0 qkv)
    f2h1_kernel<<<SEQ * DM / 4 / 256, 256>>>((const float4*)hid, (uint2*)h16);
    f2h4_kernel<<<dim3(NLAYERS * DM * DM / 4 / 256, 1, 4), 256>>>(
        (const float4*)Wq, (const float4*)Wk, (const float4*)Wv, (const float4*)Wo,
        (uint2*)wq16, (uint2*)wk16, (uint2*)wv16, (uint2*)wo16);

    const __half* h = h16;
    for (int l = 0; l < NLAYERS; l++) {
        const size_t wofs  = (size_t)l * DM * DM;
        const size_t wiofs = (size_t)l * DFF * DM;

        // fused Q/K/V projections
        hqkv_kernel<<<dim3(12, 8, 3), 256, GEMM_SMEM>>>(
            h, wq16 + wofs, wk16 + wofs, wv16 + wofs,
            bq + l * 768, bk + l * 768, bv + l * 768, q, k, vt);

        // logits = q @ k^T (fp32 out)
        hgemm_g<0, 1><<<dim3(16, 8, 12), 256, GEMM_SMEM>>>(
            q, k, nullptr, scores, 64, 1024, 65536LL, 65536LL, 1048576LL);

        // + rel term + mask + softmax -> fp16 probs
        if (l == 0) {
            rs0_kernel<<<1024, 256, RS0_SMEM>>>(
                (const float4*)rel, (const float4*)rel2, (const float4*)rela,
                (uint2*)relsum, q, scores, probs, mask);
        } else {
            rel_softmax_kernel<<<1024, 256, RS_SMEM>>>(relsum, q, scores, probs, mask);
        }

        // ctx = probs @ v  (split-K=2)
        hgemm_pv<<<dim3(2, 8, 12), 256, GEMM_SMEM>>>(probs, vt, part);
        pv_reduce<<<768, 256>>>((const float4*)part, (uint2*)ctx);

        // output projection: split-K=2, reduce+bias+residual+LN fused
        hgemm_sk<<<dim3(12, 8, 2), 256, GEMM_SMEM>>>(ctx, wo16 + wofs, part, 768, 384);
        ln_red_kernel<2, 0><<<1024, 256>>>(part, bo + l * 768, h,
                                           g1 + l * 768, b1 + l * 768, attn);

        // join FFN-weight conversion before first use
        if (l == 0) cudaStreamWaitEvent(0, ev_join, 0);

        // FFN
        hgemm_g<1, 0><<<dim3(48, 8, 1), 256, GEMM_SMEM>>>(
            attn, wi16 + wiofs, bi + l * 3072, inter, 768, 3072, 0, 0, 0);

        // FFN2: split-K=4, reduce+bias+residual+LN fused
        hgemm_sk<<<dim3(12, 8, 4), 256, GEMM_SMEM>>>(inter, w216 + wiofs, part, 3072, 768);
        if (l == NLAYERS - 1) {
            ln_red_kernel<4, 1><<<1024, 256>>>(part, b2 + l * 768, attn,
                                               g2 + l * 768, b2g + l * 768, d_out);
        } else {
            ln_red_kernel<4, 0><<<1024, 256>>>(part, b2 + l * 768, attn,
                                               g2 + l * 768, b2g + l * 768, hbuf);
        }
        h = hbuf;
    }
}